// round 2
// baseline (speedup 1.0000x reference)
#include <cuda_runtime.h>
#include <cstddef>

// Problem constants (fixed shapes for this problem)
#define BB 256      // batch
#define TT 2048     // time steps
#define HH 64       // hidden
#define GG 256      // 4*H gates

typedef unsigned long long u64;

// ---------------- packed f32x2 helpers (sm_100+) ----------------
__device__ __forceinline__ u64 fma2(u64 a, u64 b, u64 c) {
    u64 d;
    asm("fma.rn.f32x2 %0, %1, %2, %3;" : "=l"(d) : "l"(a), "l"(b), "l"(c));
    return d;
}
__device__ __forceinline__ u64 add2(u64 a, u64 b) {
    u64 d;
    asm("add.rn.f32x2 %0, %1, %2;" : "=l"(d) : "l"(a), "l"(b));
    return d;
}
__device__ __forceinline__ float hsum2(u64 a) {
    float lo = __uint_as_float((unsigned)(a & 0xffffffffull));
    float hi = __uint_as_float((unsigned)(a >> 32));
    return lo + hi;
}

// fast sigmoid / tanh via MUFU ex2 + rcp (≈2 ulp)
__device__ __forceinline__ float fsigmoid(float x) {
    float e = __expf(-x);
    return __fdividef(1.0f, 1.0f + e);
}
__device__ __forceinline__ float ftanh(float x) {
    float e = __expf(2.0f * x);
    return 1.0f - __fdividef(2.0f, e + 1.0f);
}

// ---------------- device scratch (no cudaMalloc allowed) ----------------
__device__ float g_y0[(size_t)BB * TT * HH];    // 128 MB, layer0 hidden outputs
__device__ float g_xp1[(size_t)BB * TT * GG];   // 512 MB, layer1 input projections
__device__ float g_y1[(size_t)BB * TT * HH];    // 128 MB, layer1 hidden outputs

// ---------------- LSTM recurrence kernel (one barrier per step) ----------------
// One CTA per batch row, 256 threads = 8 warps. Thread g owns gate row g of Whh
// (64 weights packed in 32 u64 registers). Cell state is REPLICATED per warp:
// lane owns units (lane) and (lane+32), identical bits in every warp. Each warp
// keeps a private copy of h in smem (hbuf[warp][64]) so the h-update needs only
// __syncwarp, not __syncthreads. Gate activations are staged in a ping-pong
// gate_sh buffer, interleaved [unit][i,f,g,o] so phase-2 reads one LDS.128 per
// unit. Exactly ONE __syncthreads per time step.
template <int LAYER>
__global__ __launch_bounds__(256, 2) void lstm_recur_kernel(
    const float* __restrict__ x,     // LAYER==0: input [B,T]  (unused for LAYER==1)
    const float* __restrict__ Wih,   // LAYER==0: [256,1]      (unused for LAYER==1)
    const float* __restrict__ Whh,   // [256,64] row-major
    const float* __restrict__ bih,
    const float* __restrict__ bhh,
    const float* __restrict__ h0,    // [B,64] for this layer
    const float* __restrict__ c0)    // [B,64] for this layer
{
    __shared__ __align__(16) float gate_sh[2][GG];   // ping-pong, [unit*4 + kind]
    __shared__ __align__(16) float hbuf[8][HH];      // per-warp private h copy

    const int g    = threadIdx.x;
    const int b    = blockIdx.x;
    const int wid  = g >> 5;
    const int lane = g & 31;

    // ---- load this gate's Whh row into registers (packed pairs) ----
    u64 w[32];
    {
        const ulonglong2* wr = (const ulonglong2*)(Whh + (size_t)g * HH);
#pragma unroll
        for (int i = 0; i < 16; i++) {
            ulonglong2 v = wr[i];
            w[2 * i]     = v.x;
            w[2 * i + 1] = v.y;
        }
    }
    const float bias = bih[g] + bhh[g];
    const float wih0 = (LAYER == 0) ? Wih[g] : 0.0f;
    const int gate_kind = g >> 6;           // 0:i 1:f 2:g 3:o
    const int gslot = ((g & 63) << 2) | gate_kind;   // interleaved slot

    // replicated cell state: every warp carries c for units lane and lane+32
    float cA = c0[(size_t)b * HH + lane];
    float cB = c0[(size_t)b * HH + lane + 32];
    // per-warp private h copy
    hbuf[wid][lane]      = h0[(size_t)b * HH + lane];
    hbuf[wid][lane + 32] = h0[(size_t)b * HH + lane + 32];
    __syncwarp();

    const size_t xbase0 = (size_t)b * TT;            // layer0: x[b][t]
    const size_t xbase1 = (size_t)b * TT * GG + g;   // layer1: xp1[(b,t)][g]
    float* yout = (LAYER == 0) ? g_y0 : g_y1;
    const size_t ybase = (size_t)b * TT * HH;

    // input prefetch, 2 steps deep (covers DRAM latency for layer1 stream)
    float x0, x1;
    if (LAYER == 0) {
        x0 = __ldg(x + xbase0);
        x1 = __ldg(x + xbase0 + 1);
    } else {
        x0 = __ldg(g_xp1 + xbase1);
        x1 = __ldg(g_xp1 + xbase1 + (size_t)GG);
    }

#pragma unroll 1
    for (int t = 0; t < TT; t++) {
        const int buf = t & 1;

        // ---- phase 1: gate pre-activation = bias + xp + Whh[g,:]·h ----
        u64 a0 = 0ull, a1 = 0ull, a2 = 0ull, a3 = 0ull;
        const ulonglong2* hs = (const ulonglong2*)hbuf[wid];
#pragma unroll
        for (int i = 0; i < 8; i++) {
            ulonglong2 h1 = hs[2 * i];
            ulonglong2 h2 = hs[2 * i + 1];
            a0 = fma2(w[4 * i + 0], h1.x, a0);
            a1 = fma2(w[4 * i + 1], h1.y, a1);
            a2 = fma2(w[4 * i + 2], h2.x, a2);
            a3 = fma2(w[4 * i + 3], h2.y, a3);
        }
        a0 = add2(a0, a1);
        a2 = add2(a2, a3);
        a0 = add2(a0, a2);
        float pre = bias + hsum2(a0);
        if (LAYER == 0) pre = fmaf(x0, wih0, pre);
        else            pre += x0;

        // own-gate nonlinearity (spread over all 256 threads)
        float act = (gate_kind == 2) ? ftanh(pre) : fsigmoid(pre);
        gate_sh[buf][gslot] = act;

        // rotate input prefetch (hidden behind barrier + phase2)
        x0 = x1;
        {
            int tn = (t + 2 < TT) ? (t + 2) : (TT - 1);
            if (LAYER == 0) x1 = __ldg(x + xbase0 + tn);
            else            x1 = __ldg(g_xp1 + xbase1 + (size_t)tn * GG);
        }

        __syncthreads();   // single barrier per step: gates ready

        // ---- phase 2 (redundant in every warp): update units lane, lane+32 ----
        {
            const float4* gs = (const float4*)gate_sh[buf];
            float4 gA = gs[lane];        // {i,f,g,o} for unit lane
            float4 gB = gs[lane + 32];   // {i,f,g,o} for unit lane+32
            cA = gA.y * cA + gA.x * gA.z;
            cB = gB.y * cB + gB.x * gB.z;
            float hA = gA.w * ftanh(cA);
            float hB = gB.w * ftanh(cB);
            hbuf[wid][lane]      = hA;
            hbuf[wid][lane + 32] = hB;
            if (wid == 0) {
                yout[ybase + (size_t)t * HH + lane]      = hA;
                yout[ybase + (size_t)t * HH + lane + 32] = hB;
            }
        }
        __syncwarp();   // own hbuf writes visible to own warp's next dot
    }
}

// ---------------- K2: xp1 = y0 @ Wih1^T  ([B*T,64] x [64,256] -> [B*T,256]) ----------------
#define K2_ROWS 64
__global__ __launch_bounds__(256, 2) void xp_gemm_kernel(const float* __restrict__ Wih1)
{
    __shared__ __align__(16) float ys[K2_ROWS * HH];
    const int g = threadIdx.x;

    u64 w[32];
    {
        const ulonglong2* wr = (const ulonglong2*)(Wih1 + (size_t)g * HH);
#pragma unroll
        for (int i = 0; i < 16; i++) {
            ulonglong2 v = wr[i];
            w[2 * i]     = v.x;
            w[2 * i + 1] = v.y;
        }
    }

    const size_t r0 = (size_t)blockIdx.x * K2_ROWS;
    {
        const float4* src = (const float4*)(g_y0 + r0 * HH);
        float4* dst = (float4*)ys;
#pragma unroll
        for (int i = 0; i < 4; i++) dst[g + i * 256] = src[g + i * 256];
    }
    __syncthreads();

#pragma unroll 1
    for (int r = 0; r < K2_ROWS; r++) {
        const ulonglong2* hs = (const ulonglong2*)(ys + r * HH);
        u64 a0 = 0ull, a1 = 0ull, a2 = 0ull, a3 = 0ull;
#pragma unroll
        for (int i = 0; i < 8; i++) {
            ulonglong2 h1 = hs[2 * i];
            ulonglong2 h2 = hs[2 * i + 1];
            a0 = fma2(w[4 * i + 0], h1.x, a0);
            a1 = fma2(w[4 * i + 1], h1.y, a1);
            a2 = fma2(w[4 * i + 2], h2.x, a2);
            a3 = fma2(w[4 * i + 3], h2.y, a3);
        }
        a0 = add2(a0, a1);
        a2 = add2(a2, a3);
        a0 = add2(a0, a2);
        g_xp1[(r0 + r) * GG + g] = hsum2(a0);
    }
}

// ---------------- K4: pred = y1 @ Wlin^T + blin ----------------
__global__ __launch_bounds__(256) void out_kernel(
    const float* __restrict__ Wlin,
    const float* __restrict__ blin,
    float* __restrict__ out)
{
    __shared__ __align__(16) float wl[HH];
    const int tid = threadIdx.x;
    if (tid < HH) wl[tid] = Wlin[tid];
    __syncthreads();

    const size_t idx = (size_t)blockIdx.x * 256 + tid;
    const ulonglong2* row = (const ulonglong2*)(g_y1 + idx * HH);
    const ulonglong2* wv  = (const ulonglong2*)wl;
    u64 a0 = 0ull, a1 = 0ull, a2 = 0ull, a3 = 0ull;
#pragma unroll
    for (int i = 0; i < 8; i++) {
        ulonglong2 h1 = row[2 * i];
        ulonglong2 w1 = wv[2 * i];
        ulonglong2 h2 = row[2 * i + 1];
        ulonglong2 w2 = wv[2 * i + 1];
        a0 = fma2(w1.x, h1.x, a0);
        a1 = fma2(w1.y, h1.y, a1);
        a2 = fma2(w2.x, h2.x, a2);
        a3 = fma2(w2.y, h2.y, a3);
    }
    a0 = add2(a0, a1);
    a2 = add2(a2, a3);
    a0 = add2(a0, a2);
    out[idx] = hsum2(a0) + __ldg(blin);
}

// ---------------- launch ----------------
extern "C" void kernel_launch(void* const* d_in, const int* in_sizes, int n_in,
                              void* d_out, int out_size)
{
    const float* input = (const float*)d_in[0];   // [B,T]
    const float* h0    = (const float*)d_in[1];   // [2,B,H]
    const float* c0    = (const float*)d_in[2];   // [2,B,H]
    const float* Wih0  = (const float*)d_in[3];   // [256,1]
    const float* Whh0  = (const float*)d_in[4];   // [256,64]
    const float* bih0  = (const float*)d_in[5];
    const float* bhh0  = (const float*)d_in[6];
    const float* Wih1  = (const float*)d_in[7];   // [256,64]
    const float* Whh1  = (const float*)d_in[8];   // [256,64]
    const float* bih1  = (const float*)d_in[9];
    const float* bhh1  = (const float*)d_in[10];
    const float* Wlin  = (const float*)d_in[11];  // [1,64]
    const float* blin  = (const float*)d_in[12];  // [1]
    float* out = (float*)d_out;                   // [B,T]

    (void)in_sizes; (void)n_in; (void)out_size;

    // Layer 0 recurrence -> g_y0
    lstm_recur_kernel<0><<<BB, 256>>>(input, Wih0, Whh0, bih0, bhh0,
                                      h0, c0);
    // xp1 = y0 @ Wih1^T  -> g_xp1
    xp_gemm_kernel<<<(BB * TT) / K2_ROWS, 256>>>(Wih1);
    // Layer 1 recurrence -> g_y1
    lstm_recur_kernel<1><<<BB, 256>>>(input /*unused*/, Wih1 /*unused*/, Whh1,
                                      bih1, bhh1,
                                      h0 + (size_t)BB * HH, c0 + (size_t)BB * HH);
    // pred = y1 @ Wlin^T + blin
    out_kernel<<<(BB * TT) / 256, 256>>>(Wlin, blin, out);
}

// round 3
// speedup vs baseline: 1.0575x; 1.0575x over previous
#include <cuda_runtime.h>
#include <cuda_fp16.h>
#include <cstddef>

#define BB 256      // batch
#define TT 2048     // time steps
#define HH 64       // hidden
#define GG 256      // 4*H gates

typedef unsigned long long u64;

// ---------------- packed f32x2 helpers (sm_100+) ----------------
__device__ __forceinline__ u64 fma2(u64 a, u64 b, u64 c) {
    u64 d;
    asm("fma.rn.f32x2 %0, %1, %2, %3;" : "=l"(d) : "l"(a), "l"(b), "l"(c));
    return d;
}
__device__ __forceinline__ u64 add2(u64 a, u64 b) {
    u64 d;
    asm("add.rn.f32x2 %0, %1, %2;" : "=l"(d) : "l"(a), "l"(b));
    return d;
}
__device__ __forceinline__ float hsum2(u64 a) {
    float lo = __uint_as_float((unsigned)(a & 0xffffffffull));
    float hi = __uint_as_float((unsigned)(a >> 32));
    return lo + hi;
}

// precise-enough sigmoid / tanh via MUFU ex2 + rcp (~2 ulp)
__device__ __forceinline__ float fsigmoid(float x) {
    float e = __expf(-x);
    return __fdividef(1.0f, 1.0f + e);
}
__device__ __forceinline__ float ftanh(float x) {
    float e = __expf(2.0f * x);
    return 1.0f - __fdividef(2.0f, e + 1.0f);
}

// ---------------- device scratch (no cudaMalloc allowed) ----------------
__device__ float  g_y0[(size_t)BB * TT * HH];    // 128 MB, layer0 hidden outputs
__device__ __half g_xp1[(size_t)BB * TT * GG];   // 256 MB, layer1 input projections (fp16)

// ---------------- LSTM recurrence kernel ----------------
// One CTA per batch row, 128 threads = 4 warps. Thread t owns gate rows t and
// t+128 (so thread u<64 holds gates i[u] (row u) and g[u] (row u+128) locally;
// thread u+64 holds f[u] (row u+64) and o[u] (row u+192)).
// The 16 LDS.128 h-loads per thread feed 32 fma2 (both rows) -> halved LDS.
// Phase 2: threads 0..63 own unit u: i,g local; (f,o) read as one LDS.64 from
// act_sh[u] written by thread u+64. Layer 1 additionally reduces Wlin·h per
// step with warp shuffles and writes the final output directly.
template <int LAYER>
__global__ __launch_bounds__(128, 2) void lstm_recur_kernel(
    const float* __restrict__ x,     // LAYER==0: input [B,T]
    const float* __restrict__ Wih,   // LAYER==0: [256,1]
    const float* __restrict__ Whh,   // [256,64] row-major
    const float* __restrict__ bih,
    const float* __restrict__ bhh,
    const float* __restrict__ h0,    // [B,64] (already offset per layer)
    const float* __restrict__ c0,    // [B,64]
    const float* __restrict__ Wlin,  // [1,64]   (LAYER==1 only)
    const float* __restrict__ blin,  // [1]      (LAYER==1 only)
    float* __restrict__ out)         // [B,T]    (LAYER==1 only)
{
    __shared__ __align__(16) float  h_sh[HH];
    __shared__ __align__(8)  float2 act_sh[HH];   // (f,o) per unit, written by threads 64..127
    __shared__ float red[2];

    const int tid  = threadIdx.x;
    const int b    = blockIdx.x;
    const int lane = tid & 31;
    const int g0   = tid;          // row in [0,128): i (0-63) / f (64-127) -> sigmoid
    const int g1   = tid + 128;    // row in [128,256): g (128-191) tanh / o (192-255) sigmoid
    const bool g1_is_tanh = (tid < 64);

    // ---- load both Whh rows into registers (packed pairs) ----
    u64 w0[32], w1[32];
    {
        const ulonglong2* r0 = (const ulonglong2*)(Whh + (size_t)g0 * HH);
        const ulonglong2* r1 = (const ulonglong2*)(Whh + (size_t)g1 * HH);
#pragma unroll
        for (int i = 0; i < 16; i++) {
            ulonglong2 v0 = r0[i];
            ulonglong2 v1 = r1[i];
            w0[2 * i] = v0.x; w0[2 * i + 1] = v0.y;
            w1[2 * i] = v1.x; w1[2 * i + 1] = v1.y;
        }
    }
    const float bias0 = bih[g0] + bhh[g0];
    const float bias1 = bih[g1] + bhh[g1];
    const float wx0 = (LAYER == 0) ? Wih[g0] : 0.0f;
    const float wx1 = (LAYER == 0) ? Wih[g1] : 0.0f;
    const float wl  = (LAYER == 1 && tid < HH) ? Wlin[tid] : 0.0f;
    const float bl  = (LAYER == 1) ? blin[0] : 0.0f;

    float c = 0.0f;
    if (tid < HH) {
        h_sh[tid] = h0[(size_t)b * HH + tid];
        c         = c0[(size_t)b * HH + tid];
    }
    __syncthreads();

    const size_t xbase0 = (size_t)b * TT;            // layer0: x[b][t]
    const size_t xbase1 = (size_t)b * TT * GG;       // layer1: xp1[(b,t)][g]
    const size_t ybase  = (size_t)b * TT * HH;       // layer0 y0 out
    const size_t obase  = (size_t)b * TT;            // layer1 out

    // input prefetch (2 steps deep)
    float xa0, xa1;   // for row g0 at t, t+1
    float xb0, xb1;   // for row g1 at t, t+1
    if (LAYER == 0) {
        float v0 = __ldg(x + xbase0);
        float v1 = __ldg(x + xbase0 + 1);
        xa0 = v0 * wx0; xb0 = v0 * wx1;
        xa1 = v1 * wx0; xb1 = v1 * wx1;
    } else {
        xa0 = __half2float(__ldg(g_xp1 + xbase1 + g0));
        xb0 = __half2float(__ldg(g_xp1 + xbase1 + g1));
        xa1 = __half2float(__ldg(g_xp1 + xbase1 + (size_t)GG + g0));
        xb1 = __half2float(__ldg(g_xp1 + xbase1 + (size_t)GG + g1));
    }

#pragma unroll 1
    for (int t = 0; t < TT; t++) {
        // ---- phase 1: two gate pre-activations sharing the h loads ----
        u64 a0 = 0ull, a1 = 0ull, a2 = 0ull, a3 = 0ull;
        u64 c0r = 0ull, c1r = 0ull, c2r = 0ull, c3r = 0ull;
        const ulonglong2* hs = (const ulonglong2*)h_sh;
#pragma unroll
        for (int i = 0; i < 8; i++) {
            ulonglong2 h1 = hs[2 * i];
            ulonglong2 h2 = hs[2 * i + 1];
            a0  = fma2(w0[4 * i + 0], h1.x, a0);
            c0r = fma2(w1[4 * i + 0], h1.x, c0r);
            a1  = fma2(w0[4 * i + 1], h1.y, a1);
            c1r = fma2(w1[4 * i + 1], h1.y, c1r);
            a2  = fma2(w0[4 * i + 2], h2.x, a2);
            c2r = fma2(w1[4 * i + 2], h2.x, c2r);
            a3  = fma2(w0[4 * i + 3], h2.y, a3);
            c3r = fma2(w1[4 * i + 3], h2.y, c3r);
        }
        a0  = add2(a0, a1);   a2  = add2(a2, a3);   a0  = add2(a0, a2);
        c0r = add2(c0r, c1r); c2r = add2(c2r, c3r); c0r = add2(c0r, c2r);
        float pre0 = bias0 + xa0 + hsum2(a0);
        float pre1 = bias1 + xb0 + hsum2(c0r);

        // activations: row g0 always sigmoid; row g1 tanh for tid<64 else sigmoid
        float act0 = fsigmoid(pre0);
        float act1 = g1_is_tanh ? ftanh(pre1) : fsigmoid(pre1);

        if (tid >= 64) act_sh[tid - 64] = make_float2(act0, act1);  // (f,o) of unit tid-64

        // rotate input prefetch
        xa0 = xa1; xb0 = xb1;
        {
            int tn = (t + 2 < TT) ? (t + 2) : (TT - 1);
            if (LAYER == 0) {
                float v = __ldg(x + xbase0 + tn);
                xa1 = v * wx0; xb1 = v * wx1;
            } else {
                xa1 = __half2float(__ldg(g_xp1 + xbase1 + (size_t)tn * GG + g0));
                xb1 = __half2float(__ldg(g_xp1 + xbase1 + (size_t)tn * GG + g1));
            }
        }

        __syncthreads();   // (f,o) staged; h_sh reads of this step done

        // ---- phase 2: threads 0..63 update unit tid ----
        if (tid < 64) {
            float2 fo = act_sh[tid];
            c = fo.x * c + act0 * act1;      // f*c + i*g
            float hv = fo.y * ftanh(c);      // o*tanh(c)
            h_sh[tid] = hv;
            if (LAYER == 0) {
                g_y0[ybase + (size_t)t * HH + tid] = hv;
            } else {
                float p = wl * hv;
#pragma unroll
                for (int s = 16; s > 0; s >>= 1)
                    p += __shfl_xor_sync(0xffffffffu, p, s);
                if (lane == 0) red[tid >> 5] = p;
            }
        }
        __syncthreads();   // h ready for next step (and red[] visible)

        if (LAYER == 1 && tid == 64) {
            out[obase + t] = red[0] + red[1] + bl;
        }
    }
}

// ---------------- K2: xp1 = y0 @ Wih1^T -> fp16 ----------------
#define K2_ROWS 64
__global__ __launch_bounds__(256, 2) void xp_gemm_kernel(const float* __restrict__ Wih1)
{
    __shared__ __align__(16) float ys[K2_ROWS * HH];
    const int g = threadIdx.x;

    u64 w[32];
    {
        const ulonglong2* wr = (const ulonglong2*)(Wih1 + (size_t)g * HH);
#pragma unroll
        for (int i = 0; i < 16; i++) {
            ulonglong2 v = wr[i];
            w[2 * i]     = v.x;
            w[2 * i + 1] = v.y;
        }
    }

    const size_t r0 = (size_t)blockIdx.x * K2_ROWS;
    {
        const float4* src = (const float4*)(g_y0 + r0 * HH);
        float4* dst = (float4*)ys;
#pragma unroll
        for (int i = 0; i < 4; i++) dst[g + i * 256] = src[g + i * 256];
    }
    __syncthreads();

#pragma unroll 1
    for (int r = 0; r < K2_ROWS; r++) {
        const ulonglong2* hs = (const ulonglong2*)(ys + r * HH);
        u64 a0 = 0ull, a1 = 0ull, a2 = 0ull, a3 = 0ull;
#pragma unroll
        for (int i = 0; i < 8; i++) {
            ulonglong2 h1 = hs[2 * i];
            ulonglong2 h2 = hs[2 * i + 1];
            a0 = fma2(w[4 * i + 0], h1.x, a0);
            a1 = fma2(w[4 * i + 1], h1.y, a1);
            a2 = fma2(w[4 * i + 2], h2.x, a2);
            a3 = fma2(w[4 * i + 3], h2.y, a3);
        }
        a0 = add2(a0, a1);
        a2 = add2(a2, a3);
        a0 = add2(a0, a2);
        g_xp1[(r0 + r) * GG + g] = __float2half_rn(hsum2(a0));
    }
}

// ---------------- launch ----------------
extern "C" void kernel_launch(void* const* d_in, const int* in_sizes, int n_in,
                              void* d_out, int out_size)
{
    const float* input = (const float*)d_in[0];   // [B,T]
    const float* h0    = (const float*)d_in[1];   // [2,B,H]
    const float* c0    = (const float*)d_in[2];   // [2,B,H]
    const float* Wih0  = (const float*)d_in[3];   // [256,1]
    const float* Whh0  = (const float*)d_in[4];   // [256,64]
    const float* bih0  = (const float*)d_in[5];
    const float* bhh0  = (const float*)d_in[6];
    const float* Wih1  = (const float*)d_in[7];   // [256,64]
    const float* Whh1  = (const float*)d_in[8];   // [256,64]
    const float* bih1  = (const float*)d_in[9];
    const float* bhh1  = (const float*)d_in[10];
    const float* Wlin  = (const float*)d_in[11];  // [1,64]
    const float* blin  = (const float*)d_in[12];  // [1]
    float* out = (float*)d_out;                   // [B,T]

    (void)in_sizes; (void)n_in; (void)out_size;

    // Layer 0 recurrence -> g_y0
    lstm_recur_kernel<0><<<BB, 128>>>(input, Wih0, Whh0, bih0, bhh0,
                                      h0, c0, Wlin, blin, out);
    // xp1 = y0 @ Wih1^T -> g_xp1 (fp16)
    xp_gemm_kernel<<<(BB * TT) / K2_ROWS, 256>>>(Wih1);
    // Layer 1 recurrence (+ fused output linear) -> out
    lstm_recur_kernel<1><<<BB, 128>>>(input /*unused*/, Wih0 /*unused*/, Whh1,
                                      bih1, bhh1,
                                      h0 + (size_t)BB * HH, c0 + (size_t)BB * HH,
                                      Wlin, blin, out);
}

// round 4
// speedup vs baseline: 1.4850x; 1.4042x over previous
#include <cuda_runtime.h>
#include <cuda_fp16.h>
#include <cstddef>

#define BB 256      // batch
#define TT 2048     // time steps
#define HH 64       // hidden
#define GG 256      // 4*H gates

typedef unsigned long long u64;

// ---------------- packed f32x2 helpers (sm_100+) ----------------
__device__ __forceinline__ u64 fma2(u64 a, u64 b, u64 c) {
    u64 d;
    asm("fma.rn.f32x2 %0, %1, %2, %3;" : "=l"(d) : "l"(a), "l"(b), "l"(c));
    return d;
}
__device__ __forceinline__ u64 add2(u64 a, u64 b) {
    u64 d;
    asm("add.rn.f32x2 %0, %1, %2;" : "=l"(d) : "l"(a), "l"(b));
    return d;
}
__device__ __forceinline__ float hsum2(u64 a) {
    float lo = __uint_as_float((unsigned)(a & 0xffffffffull));
    float hi = __uint_as_float((unsigned)(a >> 32));
    return lo + hi;
}

// MUFU-based fast activations (sm_75+ tanh.approx, single MUFU op)
__device__ __forceinline__ float tanh_ap(float x) {
    float y;
    asm("tanh.approx.f32 %0, %1;" : "=f"(y) : "f"(x));
    return y;
}
__device__ __forceinline__ float sig_ap(float x) {
    return fmaf(0.5f, tanh_ap(0.5f * x), 0.5f);
}

// ---------------- device scratch (no cudaMalloc allowed) ----------------
__device__ float  g_y0[(size_t)BB * TT * HH];    // 128 MB, layer0 hidden outputs
__device__ __half g_xp1[(size_t)BB * TT * GG];   // 256 MB, layer1 input projections (fp16)
__device__ float  g_y1[(size_t)BB * TT * HH];    // 128 MB, layer1 hidden outputs

// ---------------- LSTM recurrence kernel ----------------
// One CTA per batch row, 128 threads = 4 warps. Thread t owns gate rows t and
// t+128: thread u<64 holds gates i[u],g[u]; thread u+64 holds f[u],o[u].
// Phase 1: 16 LDS.128 h-loads feed 32 fma2 (both rows). Threads>=64 stage
// (f,o) via one STS.64; after one barrier threads<64 update c,h (one LDS.64),
// second barrier publishes h. Activations use MUFU tanh.approx.
// Input stream prefetched 4 steps deep (covers NAT DRAM latency).
template <int LAYER>
__global__ __launch_bounds__(128, 2) void lstm_recur_kernel(
    const float* __restrict__ x,     // LAYER==0: input [B,T]
    const float* __restrict__ Wih,   // LAYER==0: [256,1]
    const float* __restrict__ Whh,   // [256,64] row-major
    const float* __restrict__ bih,
    const float* __restrict__ bhh,
    const float* __restrict__ h0,    // [B,64] (already offset per layer)
    const float* __restrict__ c0)    // [B,64]
{
    __shared__ __align__(16) float  h_sh[HH];
    __shared__ __align__(8)  float2 act_sh[HH];   // (f,o) per unit

    const int tid  = threadIdx.x;
    const int b    = blockIdx.x;
    const int g0   = tid;          // rows 0-63: i, 64-127: f   (sigmoid)
    const int g1   = tid + 128;    // rows 128-191: g (tanh), 192-255: o (sigmoid)
    const bool g1_is_tanh = (tid < 64);

    // ---- load both Whh rows into registers (packed pairs) ----
    u64 w0[32], w1[32];
    {
        const ulonglong2* r0 = (const ulonglong2*)(Whh + (size_t)g0 * HH);
        const ulonglong2* r1 = (const ulonglong2*)(Whh + (size_t)g1 * HH);
#pragma unroll
        for (int i = 0; i < 16; i++) {
            ulonglong2 v0 = r0[i];
            ulonglong2 v1 = r1[i];
            w0[2 * i] = v0.x; w0[2 * i + 1] = v0.y;
            w1[2 * i] = v1.x; w1[2 * i + 1] = v1.y;
        }
    }
    const float bias0 = bih[g0] + bhh[g0];
    const float bias1 = bih[g1] + bhh[g1];
    const float wx0 = (LAYER == 0) ? Wih[g0] : 0.0f;
    const float wx1 = (LAYER == 0) ? Wih[g1] : 0.0f;

    float c = 0.0f;
    if (tid < HH) {
        h_sh[tid] = h0[(size_t)b * HH + tid];
        c         = c0[(size_t)b * HH + tid];
    }
    __syncthreads();

    const size_t xbase0 = (size_t)b * TT;            // layer0: x[b][t]
    const size_t xbase1 = (size_t)b * TT * GG;       // layer1: xp1[(b,t)][g]
    float* yout = (LAYER == 0) ? g_y0 : g_y1;
    const size_t ybase = (size_t)b * TT * HH;

    // ---- input prefetch, 4 steps deep ----
    float xa[4], xb[4];
#pragma unroll
    for (int k = 0; k < 4; k++) {
        if (LAYER == 0) {
            float v = __ldg(x + xbase0 + k);
            xa[k] = v * wx0; xb[k] = v * wx1;
        } else {
            xa[k] = __half2float(__ldg(g_xp1 + xbase1 + (size_t)k * GG + g0));
            xb[k] = __half2float(__ldg(g_xp1 + xbase1 + (size_t)k * GG + g1));
        }
    }

#pragma unroll 4
    for (int t = 0; t < TT; t++) {
        // ---- phase 1: two gate pre-activations sharing the h loads ----
        u64 a0 = 0ull, a1 = 0ull, a2 = 0ull, a3 = 0ull;
        u64 d0 = 0ull, d1 = 0ull, d2 = 0ull, d3 = 0ull;
        const ulonglong2* hs = (const ulonglong2*)h_sh;
#pragma unroll
        for (int i = 0; i < 8; i++) {
            ulonglong2 h1 = hs[2 * i];
            ulonglong2 h2 = hs[2 * i + 1];
            a0 = fma2(w0[4 * i + 0], h1.x, a0);
            d0 = fma2(w1[4 * i + 0], h1.x, d0);
            a1 = fma2(w0[4 * i + 1], h1.y, a1);
            d1 = fma2(w1[4 * i + 1], h1.y, d1);
            a2 = fma2(w0[4 * i + 2], h2.x, a2);
            d2 = fma2(w1[4 * i + 2], h2.x, d2);
            a3 = fma2(w0[4 * i + 3], h2.y, a3);
            d3 = fma2(w1[4 * i + 3], h2.y, d3);
        }
        a0 = add2(a0, a1); a2 = add2(a2, a3); a0 = add2(a0, a2);
        d0 = add2(d0, d1); d2 = add2(d2, d3); d0 = add2(d0, d2);
        float pre0 = bias0 + xa[0] + hsum2(a0);
        float pre1 = bias1 + xb[0] + hsum2(d0);

        float act0 = sig_ap(pre0);                                // i or f
        float act1 = g1_is_tanh ? tanh_ap(pre1) : sig_ap(pre1);   // g or o

        if (tid >= 64) act_sh[tid - 64] = make_float2(act0, act1);  // (f,o)

        // rotate prefetch window (register-renamed under unroll)
        xa[0] = xa[1]; xa[1] = xa[2]; xa[2] = xa[3];
        xb[0] = xb[1]; xb[1] = xb[2]; xb[2] = xb[3];
        {
            int tn = (t + 4 < TT) ? (t + 4) : (TT - 1);
            if (LAYER == 0) {
                float v = __ldg(x + xbase0 + tn);
                xa[3] = v * wx0; xb[3] = v * wx1;
            } else {
                xa[3] = __half2float(__ldg(g_xp1 + xbase1 + (size_t)tn * GG + g0));
                xb[3] = __half2float(__ldg(g_xp1 + xbase1 + (size_t)tn * GG + g1));
            }
        }

        __syncthreads();   // (f,o) staged; h_sh reads of this step done

        // ---- phase 2: threads 0..63 update unit tid ----
        if (tid < 64) {
            float2 fo = act_sh[tid];
            c = fmaf(fo.x, c, act0 * act1);      // f*c + i*g
            float hv = fo.y * tanh_ap(c);        // o*tanh(c)
            h_sh[tid] = hv;
            yout[ybase + (size_t)t * HH + tid] = hv;
        }
        __syncthreads();   // h ready for next step
    }
}

// ---------------- K2: xp1 = y0 @ Wih1^T -> fp16 ----------------
#define K2_ROWS 64
__global__ __launch_bounds__(256, 2) void xp_gemm_kernel(const float* __restrict__ Wih1)
{
    __shared__ __align__(16) float ys[K2_ROWS * HH];
    const int g = threadIdx.x;

    u64 w[32];
    {
        const ulonglong2* wr = (const ulonglong2*)(Wih1 + (size_t)g * HH);
#pragma unroll
        for (int i = 0; i < 16; i++) {
            ulonglong2 v = wr[i];
            w[2 * i]     = v.x;
            w[2 * i + 1] = v.y;
        }
    }

    const size_t r0 = (size_t)blockIdx.x * K2_ROWS;
    {
        const float4* src = (const float4*)(g_y0 + r0 * HH);
        float4* dst = (float4*)ys;
#pragma unroll
        for (int i = 0; i < 4; i++) dst[g + i * 256] = src[g + i * 256];
    }
    __syncthreads();

#pragma unroll 1
    for (int r = 0; r < K2_ROWS; r++) {
        const ulonglong2* hs = (const ulonglong2*)(ys + r * HH);
        u64 a0 = 0ull, a1 = 0ull, a2 = 0ull, a3 = 0ull;
#pragma unroll
        for (int i = 0; i < 8; i++) {
            ulonglong2 h1 = hs[2 * i];
            ulonglong2 h2 = hs[2 * i + 1];
            a0 = fma2(w[4 * i + 0], h1.x, a0);
            a1 = fma2(w[4 * i + 1], h1.y, a1);
            a2 = fma2(w[4 * i + 2], h2.x, a2);
            a3 = fma2(w[4 * i + 3], h2.y, a3);
        }
        a0 = add2(a0, a1);
        a2 = add2(a2, a3);
        a0 = add2(a0, a2);
        g_xp1[(r0 + r) * GG + g] = __float2half_rn(hsum2(a0));
    }
}

// ---------------- K4: pred = y1 @ Wlin^T + blin ----------------
__global__ __launch_bounds__(256) void out_kernel(
    const float* __restrict__ Wlin,
    const float* __restrict__ blin,
    float* __restrict__ out)
{
    __shared__ __align__(16) float wl[HH];
    const int tid = threadIdx.x;
    if (tid < HH) wl[tid] = Wlin[tid];
    __syncthreads();

    const size_t idx = (size_t)blockIdx.x * 256 + tid;
    const ulonglong2* row = (const ulonglong2*)(g_y1 + idx * HH);
    const ulonglong2* wv  = (const ulonglong2*)wl;
    u64 a0 = 0ull, a1 = 0ull, a2 = 0ull, a3 = 0ull;
#pragma unroll
    for (int i = 0; i < 8; i++) {
        ulonglong2 h1 = row[2 * i];
        ulonglong2 w1 = wv[2 * i];
        ulonglong2 h2 = row[2 * i + 1];
        ulonglong2 w2 = wv[2 * i + 1];
        a0 = fma2(w1.x, h1.x, a0);
        a1 = fma2(w1.y, h1.y, a1);
        a2 = fma2(w2.x, h2.x, a2);
        a3 = fma2(w2.y, h2.y, a3);
    }
    a0 = add2(a0, a1);
    a2 = add2(a2, a3);
    a0 = add2(a0, a2);
    out[idx] = hsum2(a0) + __ldg(blin);
}

// ---------------- launch ----------------
extern "C" void kernel_launch(void* const* d_in, const int* in_sizes, int n_in,
                              void* d_out, int out_size)
{
    const float* input = (const float*)d_in[0];   // [B,T]
    const float* h0    = (const float*)d_in[1];   // [2,B,H]
    const float* c0    = (const float*)d_in[2];   // [2,B,H]
    const float* Wih0  = (const float*)d_in[3];   // [256,1]
    const float* Whh0  = (const float*)d_in[4];   // [256,64]
    const float* bih0  = (const float*)d_in[5];
    const float* bhh0  = (const float*)d_in[6];
    const float* Wih1  = (const float*)d_in[7];   // [256,64]
    const float* Whh1  = (const float*)d_in[8];   // [256,64]
    const float* bih1  = (const float*)d_in[9];
    const float* bhh1  = (const float*)d_in[10];
    const float* Wlin  = (const float*)d_in[11];  // [1,64]
    const float* blin  = (const float*)d_in[12];  // [1]
    float* out = (float*)d_out;                   // [B,T]

    (void)in_sizes; (void)n_in; (void)out_size;

    // Layer 0 recurrence -> g_y0
    lstm_recur_kernel<0><<<BB, 128>>>(input, Wih0, Whh0, bih0, bhh0, h0, c0);
    // xp1 = y0 @ Wih1^T -> g_xp1 (fp16)
    xp_gemm_kernel<<<(BB * TT) / K2_ROWS, 256>>>(Wih1);
    // Layer 1 recurrence -> g_y1
    lstm_recur_kernel<1><<<BB, 128>>>(input /*unused*/, Wih0 /*unused*/, Whh1,
                                      bih1, bhh1,
                                      h0 + (size_t)BB * HH, c0 + (size_t)BB * HH);
    // pred = y1 @ Wlin^T + blin
    out_kernel<<<(BB * TT) / 256, 256>>>(Wlin, blin, out);
}